// round 6
// baseline (speedup 1.0000x reference)
#include <cuda_runtime.h>
#include <math.h>

#define TT 8192
#define NN 4096
#define LL 64
#define PP 32
#define INDIM 192
#define NBLK_C 2048          // (4096/128) * (8192/128)

// ---------------- device scratch (no allocations allowed) ----------------
__device__ float g_Q[128 * LL * LL];     // Q_b = M^b, b=1..128 (slot b-1)
__device__ float g_W[LL * 64];           // W[l][a] = (M^{128a} x0)[l], a=0..63
__device__ float g_xhT[LL * TT];         // xh_seq transposed: [l][t]
__device__ float g_Ut[LL * NN];          // U transposed: [l][n]
__device__ int   g_sel[PP];
__device__ float g_newtemp;
__device__ float g_part[NBLK_C * 2];
__device__ int   g_cnt;

// ---------------- packed f32x2 helpers (Blackwell) ----------------
__device__ __forceinline__ unsigned long long pack2(float x) {
    unsigned long long r;
    asm("mov.b64 %0, {%1, %1};" : "=l"(r) : "f"(x));
    return r;
}
__device__ __forceinline__ void fma2(unsigned long long& d,
                                     unsigned long long a,
                                     unsigned long long b) {
    asm("fma.rn.f32x2 %0, %1, %2, %0;" : "+l"(d) : "l"(a), "l"(b));
}
__device__ __forceinline__ float2 u2f(unsigned long long v) {
    float2 f;
    asm("mov.b64 {%0, %1}, %2;" : "=f"(f.x), "=f"(f.y) : "l"(v));
    return f;
}

// ============================================================================
// kSetup (1 block): sel, new_temp, M=Q_1, xh0 -> g_W col 0, zero g_cnt.
// ============================================================================
__global__ __launch_bounds__(256) void kSetup(const float* __restrict__ Xtr,
                                              const float* __restrict__ temp,
                                              const float* __restrict__ phi,
                                              const float* __restrict__ Atil,
                                              const float* __restrict__ U,
                                              const float* __restrict__ logits) {
    __shared__ float sM[LL * LL];
    __shared__ float sPart[16 * LL];
    __shared__ int   ssel[PP];
    const int tid = threadIdx.x;

    if (tid == 0) {
        g_newtemp = fmaxf(0.01f, temp[0] * 0.999f);
        g_cnt = 0;
    }
    // argmax per logits row (first max, matches jnp.argmax)
    if (tid < PP) {
        const float* row = logits + tid * INDIM;
        float best = row[0];
        int bi = 0;
        for (int j = 1; j < INDIM; j++) {
            float v = row[j];
            if (v > best) { best = v; bi = j; }
        }
        ssel[tid] = bi;
        g_sel[tid] = bi;
    }

    // M = A_tilde + phi_bar @ G  (clipped gather columns)
    for (int idx = tid; idx < LL * LL; idx += 256) sM[idx] = Atil[idx];
    __syncthreads();
    if (tid < LL) {
        float* mrow = &sM[tid * LL];
        for (int p = 0; p < PP; p++) {
            int j = ssel[p];
            if (j > LL - 1) j = LL - 1;          // mode='clip'
            mrow[j] += phi[p * LL + tid];        // phi_bar[i][p] = phi_t[p][i]
        }
    }
    __syncthreads();
    for (int idx = tid; idx < LL * LL; idx += 256) g_Q[idx] = sM[idx];  // Q_1

    // xh0 = U^T x0  (x0 = first row of X_train)
    {
        const int lq = tid & 15, g = tid >> 4;
        float4 acc = make_float4(0.f, 0.f, 0.f, 0.f);
        const float4* U4 = (const float4*)U;
        const int nbeg = g * 256;
        for (int n = nbeg; n < nbeg + 256; n++) {
            float4 u = U4[n * 16 + lq];
            float x = Xtr[n];
            acc.x += u.x * x; acc.y += u.y * x;
            acc.z += u.z * x; acc.w += u.w * x;
        }
        sPart[g * LL + 4 * lq + 0] = acc.x;
        sPart[g * LL + 4 * lq + 1] = acc.y;
        sPart[g * LL + 4 * lq + 2] = acc.z;
        sPart[g * LL + 4 * lq + 3] = acc.w;
    }
    __syncthreads();
    if (tid < LL) {
        float s = 0.f;
        for (int g = 0; g < 16; g++) s += sPart[g * LL + tid];  // fixed order
        g_W[tid * 64] = s;   // column a = 0
    }
}

// ============================================================================
// kPow(base): grid = base blocks. Block i computes Q_{base+i+1} = Q_base @ Q_{i+1}.
// ============================================================================
__global__ __launch_bounds__(256) void kPow(int base) {
    __shared__ __align__(16) float sA[LL * LL];
    __shared__ __align__(16) float sB[LL * LL];
    const int tid = threadIdx.x;
    const float* A = g_Q + (size_t)(base - 1) * LL * LL;
    const float* B = g_Q + (size_t)blockIdx.x * LL * LL;
    float* C = g_Q + (size_t)(base + blockIdx.x) * LL * LL;

    for (int idx = tid; idx < 1024; idx += 256) {
        ((float4*)sA)[idx] = ((const float4*)A)[idx];
        ((float4*)sB)[idx] = ((const float4*)B)[idx];
    }
    __syncthreads();

    const int ti = (tid >> 4) << 2;
    const int tj = (tid & 15) << 2;
    unsigned long long o00 = 0, o01 = 0, o10 = 0, o11 = 0;
    unsigned long long o20 = 0, o21 = 0, o30 = 0, o31 = 0;
    #pragma unroll 8
    for (int k = 0; k < LL; k++) {
        ulonglong2 bp = *(const ulonglong2*)&sB[k * LL + tj];
        unsigned long long a0 = pack2(sA[(ti + 0) * LL + k]);
        unsigned long long a1 = pack2(sA[(ti + 1) * LL + k]);
        unsigned long long a2 = pack2(sA[(ti + 2) * LL + k]);
        unsigned long long a3 = pack2(sA[(ti + 3) * LL + k]);
        fma2(o00, a0, bp.x); fma2(o01, a0, bp.y);
        fma2(o10, a1, bp.x); fma2(o11, a1, bp.y);
        fma2(o20, a2, bp.x); fma2(o21, a2, bp.y);
        fma2(o30, a3, bp.x); fma2(o31, a3, bp.y);
    }
    *(unsigned long long*)&C[(ti + 0) * LL + tj]     = o00;
    *(unsigned long long*)&C[(ti + 0) * LL + tj + 2] = o01;
    *(unsigned long long*)&C[(ti + 1) * LL + tj]     = o10;
    *(unsigned long long*)&C[(ti + 1) * LL + tj + 2] = o11;
    *(unsigned long long*)&C[(ti + 2) * LL + tj]     = o20;
    *(unsigned long long*)&C[(ti + 2) * LL + tj + 2] = o21;
    *(unsigned long long*)&C[(ti + 3) * LL + tj]     = o30;
    *(unsigned long long*)&C[(ti + 3) * LL + tj + 2] = o31;
}

// ============================================================================
// kW (1 block): w_a = Q_128 @ w_{a-1}, a = 1..63; writes g_W columns.
// ============================================================================
__global__ __launch_bounds__(256) void kW() {
    __shared__ float sv[LL];
    __shared__ float sp[4 * LL];
    const int tid = threadIdx.x;
    const int i = tid & 63, q = tid >> 6;   // 4-way k split
    const float* Mc = g_Q + (size_t)127 * LL * LL;

    float mr[16];
    #pragma unroll
    for (int kk = 0; kk < 16; kk++) mr[kk] = Mc[i * LL + q * 16 + kk];
    if (tid < LL) sv[tid] = g_W[tid * 64];   // xh0
    __syncthreads();

    for (int a = 1; a < 64; a++) {
        float a0 = 0.f, a1 = 0.f, a2 = 0.f, a3 = 0.f;
        #pragma unroll
        for (int kk = 0; kk < 16; kk += 4) {
            a0 += mr[kk + 0] * sv[q * 16 + kk + 0];
            a1 += mr[kk + 1] * sv[q * 16 + kk + 1];
            a2 += mr[kk + 2] * sv[q * 16 + kk + 2];
            a3 += mr[kk + 3] * sv[q * 16 + kk + 3];
        }
        sp[q * LL + i] = (a0 + a1) + (a2 + a3);
        __syncthreads();
        if (tid < LL) {
            float nv = (sp[i] + sp[LL + i]) + (sp[2 * LL + i] + sp[3 * LL + i]);
            sv[i] = nv;
            g_W[i * 64 + a] = nv;
        }
        __syncthreads();
    }
}

// ============================================================================
// kApply (128 blocks): block b-1 computes Q_b @ W (64x64x64) and scatters
// columns into g_xhT at t = 128a + b - 1.
// ============================================================================
__global__ __launch_bounds__(256) void kApply() {
    __shared__ __align__(16) float sA[LL * LL];
    __shared__ __align__(16) float sB[LL * LL];
    const int tid = threadIdx.x;
    const float* A = g_Q + (size_t)blockIdx.x * LL * LL;  // Q_{b}, b = bx+1

    for (int idx = tid; idx < 1024; idx += 256) {
        ((float4*)sA)[idx] = ((const float4*)A)[idx];
        ((float4*)sB)[idx] = ((const float4*)g_W)[idx];
    }
    __syncthreads();

    const int ti = (tid >> 4) << 2;   // state rows l
    const int tj = (tid & 15) << 2;   // chunk cols a
    unsigned long long o[4][2];
    #pragma unroll
    for (int r = 0; r < 4; r++) { o[r][0] = 0ull; o[r][1] = 0ull; }
    #pragma unroll 8
    for (int k = 0; k < LL; k++) {
        ulonglong2 bp = *(const ulonglong2*)&sB[k * LL + tj];
        #pragma unroll
        for (int r = 0; r < 4; r++) {
            unsigned long long ar = pack2(sA[(ti + r) * LL + k]);
            fma2(o[r][0], ar, bp.x);
            fma2(o[r][1], ar, bp.y);
        }
    }
    const int c0 = blockIdx.x;  // t = 128a + c0
    #pragma unroll
    for (int r = 0; r < 4; r++) {
        float2 lo = u2f(o[r][0]), hi = u2f(o[r][1]);
        float* dst = &g_xhT[(size_t)(ti + r) * TT + c0];
        dst[(size_t)(tj + 0) * 128] = lo.x;
        dst[(size_t)(tj + 1) * 128] = lo.y;
        dst[(size_t)(tj + 2) * 128] = hi.x;
        dst[(size_t)(tj + 3) * 128] = hi.y;
    }
}

// ============================================================================
// kT: transpose U (N,L) -> g_Ut (L,N)
// ============================================================================
__global__ __launch_bounds__(256) void kT(const float* __restrict__ U) {
    __shared__ float tile[32][33];
    const int l0 = blockIdx.x * 32;
    const int n0 = blockIdx.y * 32;
    const int x = threadIdx.x & 31;
    const int y0 = threadIdx.x >> 5;
    #pragma unroll
    for (int r = y0; r < 32; r += 8)
        tile[r][x] = U[(size_t)(n0 + r) * LL + l0 + x];
    __syncthreads();
    #pragma unroll
    for (int r = y0; r < 32; r += 8)
        g_Ut[(size_t)(l0 + r) * NN + n0 + x] = tile[x][r];
}

// ============================================================================
// kC: X_rec = xh_seq @ U^T. 128t x 128n tiles, K=64, 8x8 microtile, f32x2.
// Fused: X_rec store, Y read, residual/norm partials, last-block finalize.
// ============================================================================
__global__ __launch_bounds__(256, 2) void kC(const float* __restrict__ Y,
                                             float* __restrict__ out,
                                             int has_tail) {
    extern __shared__ __align__(16) float smem[];
    float* sA = smem;           // [k][t] 64x128
    float* sB = smem + 8192;    // [k][n] 64x128
    __shared__ int sIsLast;

    const int tid = threadIdx.x;
    const int t0 = blockIdx.y * 128;
    const int n0 = blockIdx.x * 128;

    for (int idx = tid; idx < 2048; idx += 256) {
        int k = idx >> 5, m = idx & 31;
        *(float4*)&sA[k * 128 + m * 4] =
            *(const float4*)&g_xhT[(size_t)k * TT + t0 + m * 4];
        *(float4*)&sB[k * 128 + m * 4] =
            *(const float4*)&g_Ut[(size_t)k * NN + n0 + m * 4];
    }
    __syncthreads();

    const int tx = tid & 15, ty = tid >> 4;
    const int i0 = ty * 8;     // 8 t-rows (4 f32x2 pairs)
    const int j0 = tx * 8;     // 8 n-cols

    unsigned long long acc[4][8];
    #pragma unroll
    for (int p = 0; p < 4; p++)
        #pragma unroll
        for (int c = 0; c < 8; c++) acc[p][c] = 0ull;

    #pragma unroll 8
    for (int k = 0; k < LL; k++) {
        ulonglong2 aA = *(const ulonglong2*)&sA[k * 128 + i0];
        ulonglong2 aB = *(const ulonglong2*)&sA[k * 128 + i0 + 4];
        float4 b0 = *(const float4*)&sB[k * 128 + j0];
        float4 b1 = *(const float4*)&sB[k * 128 + j0 + 4];
        unsigned long long bb[8];
        bb[0] = pack2(b0.x); bb[1] = pack2(b0.y);
        bb[2] = pack2(b0.z); bb[3] = pack2(b0.w);
        bb[4] = pack2(b1.x); bb[5] = pack2(b1.y);
        bb[6] = pack2(b1.z); bb[7] = pack2(b1.w);
        #pragma unroll
        for (int c = 0; c < 8; c++) {
            fma2(acc[0][c], aA.x, bb[c]);
            fma2(acc[1][c], aA.y, bb[c]);
            fma2(acc[2][c], aB.x, bb[c]);
            fma2(acc[3][c], aB.y, bb[c]);
        }
    }

    // Epilogue: 8 rows x 8 cols -> float4 stores + fused residual/norm.
    float s1 = 0.f, s2 = 0.f;
    #pragma unroll
    for (int p = 0; p < 4; p++) {
        float2 v[8];
        #pragma unroll
        for (int c = 0; c < 8; c++) v[c] = u2f(acc[p][c]);
        #pragma unroll
        for (int half = 0; half < 2; half++) {
            size_t off = (size_t)(t0 + i0 + 2 * p + half) * NN + n0 + j0;
            float4 va, vb;
            if (half == 0) {
                va = make_float4(v[0].x, v[1].x, v[2].x, v[3].x);
                vb = make_float4(v[4].x, v[5].x, v[6].x, v[7].x);
            } else {
                va = make_float4(v[0].y, v[1].y, v[2].y, v[3].y);
                vb = make_float4(v[4].y, v[5].y, v[6].y, v[7].y);
            }
            *(float4*)&out[off]     = va;
            *(float4*)&out[off + 4] = vb;
            float4 ya = *(const float4*)&Y[off];
            float4 yb = *(const float4*)&Y[off + 4];
            float d;
            d = ya.x - va.x; s1 += d * d; s2 += ya.x * ya.x;
            d = ya.y - va.y; s1 += d * d; s2 += ya.y * ya.y;
            d = ya.z - va.z; s1 += d * d; s2 += ya.z * ya.z;
            d = ya.w - va.w; s1 += d * d; s2 += ya.w * ya.w;
            d = yb.x - vb.x; s1 += d * d; s2 += yb.x * yb.x;
            d = yb.y - vb.y; s1 += d * d; s2 += yb.y * yb.y;
            d = yb.z - vb.z; s1 += d * d; s2 += yb.z * yb.z;
            d = yb.w - vb.w; s1 += d * d; s2 += yb.w * yb.w;
        }
    }

    __syncthreads();             // done with tiles
    float* r1 = smem;
    float* r2 = smem + 256;
    r1[tid] = s1; r2[tid] = s2;
    __syncthreads();
    #pragma unroll
    for (int s = 128; s > 0; s >>= 1) {
        if (tid < s) { r1[tid] += r1[tid + s]; r2[tid] += r2[tid + s]; }
        __syncthreads();
    }
    const int bid = blockIdx.y * 32 + blockIdx.x;
    if (tid == 0) {
        g_part[bid * 2]     = r1[0];
        g_part[bid * 2 + 1] = r2[0];
        __threadfence();
        int old = atomicAdd(&g_cnt, 1);
        sIsLast = (old == NBLK_C - 1);
    }
    __syncthreads();
    if (!sIsLast) return;

    // last block: final deterministic reduction + tail outputs
    __threadfence();
    float f1 = 0.f, f2 = 0.f;
    for (int i = tid; i < NBLK_C; i += 256) {
        f1 += g_part[2 * i];
        f2 += g_part[2 * i + 1];
    }
    r1[tid] = f1; r2[tid] = f2;
    __syncthreads();
    #pragma unroll
    for (int s = 128; s > 0; s >>= 1) {
        if (tid < s) { r1[tid] += r1[tid + s]; r2[tid] += r2[tid + s]; }
        __syncthreads();
    }
    if (!has_tail) return;
    const size_t base = (size_t)TT * NN;
    if (tid == 0) {
        out[base]     = sqrtf(r1[0] / r2[0]);
        out[base + 1] = g_newtemp;
    }
    if (tid < PP) out[base + 2 + tid] = (float)g_sel[tid];
}

extern "C" void kernel_launch(void* const* d_in, const int* in_sizes, int n_in,
                              void* d_out, int out_size) {
    const float* Xtil   = (const float*)d_in[0];  (void)Xtil;
    const float* Xtr    = (const float*)d_in[1];
    const float* Ytr    = (const float*)d_in[2];
    const float* temp   = (const float*)d_in[3];
    const float* phi    = (const float*)d_in[4];
    const float* Atil   = (const float*)d_in[5];
    const float* U      = (const float*)d_in[6];
    const float* logits = (const float*)d_in[7];
    float* out = (float*)d_out;
    const long long total = (long long)TT * NN + 2 + PP;
    const int has_tail = ((long long)out_size >= total) ? 1 : 0;

    // Unconditional (no static guard): idempotent, capture-safe non-stream API.
    cudaFuncSetAttribute(kC, cudaFuncAttributeMaxDynamicSharedMemorySize,
                         64 * 1024);

    kSetup<<<1, 256>>>(Xtr, temp, phi, Atil, U, logits);
    kT<<<dim3(2, 128), 256>>>(U);
    kPow<<<1,  256>>>(1);     // Q2
    kPow<<<2,  256>>>(2);     // Q3..Q4
    kPow<<<4,  256>>>(4);     // Q5..Q8
    kPow<<<8,  256>>>(8);     // Q9..Q16
    kPow<<<16, 256>>>(16);    // Q17..Q32
    kPow<<<32, 256>>>(32);    // Q33..Q64
    kPow<<<64, 256>>>(64);    // Q65..Q128
    kW<<<1, 256>>>();
    kApply<<<128, 256>>>();
    kC<<<dim3(32, 64), 256, 64 * 1024>>>(Ytr, out, has_tail);
}